// round 17
// baseline (speedup 1.0000x reference)
#include <cuda_runtime.h>
#include <cuda_fp16.h>
#include <stdint.h>

// Problem constants (this problem: B=1024, N=1024, T1=20000, T2=60000)
#define N_SP      1024
#define STRIDE    1025                      // half2 units; 1025 % 32 == 1 -> conflict-free
#define CAP1      128                       // 1st-order bucket cap (mean 19.5)
#define CAP2      192                       // 2nd-order bucket cap (mean 58.6)
#define ROWS_PER_CTA 64                     // 32 row-PAIRS, one pair per lane (half2)
#define PAIRS     32
#define C_SPLIT   8                         // column splits per row-group
#define COLS_PER_CTA  (N_SP / C_SPLIT)      // 128
#define COLS_PER_WARP (COLS_PER_CTA / 32)   // 4
#define SMEM_BYTES (PAIRS * STRIDE * 4)     // 131200 B (half2 = 4B)

// __device__ scratch (allocation-free per harness rules)
// cursors: [0..N_SP) = 1st-order counts, [N_SP..2*N_SP) = 2nd-order counts.
// Zeroed statically for the first call; mainK re-zeroes them at the END of each
// run (all 128 CTAs are co-resident; counts were read long before), so no
// memset node is needed and each run leaves cursors ready for the next replay.
__device__ int d_cursor[2 * N_SP];
// 1st-order records {rate_f32_bits, offA_bytes}; slots >= cnt stay zero ->
// zero-rate pads read y_sh[..+0] and contribute exactly 0.
__device__ __align__(16) uint2 d_rec1[N_SP * CAP1 + 16];
// 2nd-order records {rate_half2_dup_bits, (ia*4) | (ib*4)<<16}; rate is fp16
// duplicated into both halves so one HFMA2 applies it to both rows. Zero pads
// are exact no-ops: p*0 + c = c. +16 pad entries for quad-rounded prefetch.
__device__ __align__(16) uint2 d_rec2[N_SP * CAP2 + 16];

// ---------------- prep: bucketed scatter (1 term/thread; max atomic MLP) ---------
// Triggers PDL completion IMMEDIATELY so mainK's grid launches and runs its
// independent SMEM-fill prologue concurrently with this kernel.
__global__ void scatterK(const float* __restrict__ r1, const float* __restrict__ r2,
                         const float* __restrict__ dn,
                         const int* __restrict__ ir1,
                         const int* __restrict__ ir2a, const int* __restrict__ ir2b,
                         const int* __restrict__ io1, const int* __restrict__ io2,
                         int T1, int T2) {
    cudaTriggerProgrammaticLaunchCompletion();
    int t = blockIdx.x * blockDim.x + threadIdx.x;
    if (t >= T1 + T2) return;
    if (t < T1) {                // 1st-order: single-reactant record, fp32 rate
        float rate = r1[t];
        int ia = ir1[t], o = io1[t];
        int pos = atomicAdd(&d_cursor[o], 1);
        if (pos < CAP1)          // capacity guard (never hit for this problem's stats)
            d_rec1[o * CAP1 + pos] = make_uint2(__float_as_uint(rate),
                                                (uint32_t)(ia * 4));
    } else {                     // 2nd-order: den_norm folded in; rate -> dup half2
        int u = t - T1;
        float rate = r2[u] * dn[0];
        int ia = ir2a[u], ib = ir2b[u], o = io2[u];
        uint32_t rh = (uint32_t)__half_as_ushort(__float2half_rn(rate));
        rh |= rh << 16;
        int pos = atomicAdd(&d_cursor[N_SP + o], 1);
        if (pos < CAP2)
            d_rec2[o * CAP2 + pos] = make_uint2(rh,
                                                (uint32_t)(ia * 4) | ((uint32_t)(ib * 4) << 16));
    }
}

__device__ __forceinline__ __half2 u2h(uint32_t u) {
    __half2 h; *(uint32_t*)&h = u; return h;
}

// 2nd-order PAIR (one uint4 = 2 records): depth-2 fp16 chain, one promote.
// c = p0*r0h; c = p1*r1h + c; accA/accB += float2(c)
__device__ __forceinline__ void pair2(const char* rowp, uint4 q,
                                      float& accA, float& accB) {
    __half2 va0 = *(const __half2*)(rowp + (q.y & 0xFFFFu));
    __half2 vb0 = *(const __half2*)(rowp + (q.y >> 16));
    __half2 va1 = *(const __half2*)(rowp + (q.w & 0xFFFFu));
    __half2 vb1 = *(const __half2*)(rowp + (q.w >> 16));
    __half2 c = __hmul2(__hmul2(va0, vb0), u2h(q.x));
    c = __hfma2(__hmul2(va1, vb1), u2h(q.z), c);
    float2 f = __half22float2(c);
    accA += f.x;
    accB += f.y;
}

// 1st-order term: accA/accB += rate_f32 * va  (one LDS, fp32 path).
__device__ __forceinline__ void term1(const char* rowp, uint32_t rate_bits,
                                      uint32_t off, float& accA, float& accB) {
    __half2 va = *(const __half2*)(rowp + off);
    float2 pf = __half22float2(va);
    float r = __uint_as_float(rate_bits);
    accA = fmaf(r, pf.x, accA);
    accB = fmaf(r, pf.y, accB);
}

// ---------------- main: gather kernel (fp16 row-pair, order-split buckets) -------
// CTA = (row-group of 64 batch rows) x (column partition of 128 species).
// Lane = row-pair: y_sh[lane][spec] = half2(y[2*lane][spec], y[2*lane+1][spec]).
// PDL: the fill below overlaps scatterK; grid-dependency sync gates records.

__global__ __launch_bounds__(1024, 1)
void mainK(const float* __restrict__ y, float* __restrict__ out) {
    extern __shared__ __align__(16) char smem_raw[];
    __half2* y_sh = (__half2*)smem_raw;     // PAIRS * STRIDE half2
    int rg    = blockIdx.x / C_SPLIT;
    int cpart = blockIdx.x % C_SPLIT;
    int tid   = threadIdx.x;
    int lane  = tid & 31, w = tid >> 5;
    int cbase = cpart * COLS_PER_CTA + w * COLS_PER_WARP;

    // Fill (independent of scatterK): float4 loads per row of the pair ->
    // 4 half2 -> scalar STS (stride 1025). Overlaps scatterK under PDL.
    const float4* yb4 = (const float4*)(y + (size_t)rg * ROWS_PER_CTA * N_SP);
#pragma unroll
    for (int idx = tid; idx < PAIRS * N_SP / 4; idx += 1024) {
        int pair = idx >> 8;                       // 256 float4-slots per row
        int s4   = idx & 255;
        float4 a = yb4[(2 * pair)     * (N_SP / 4) + s4];
        float4 b = yb4[(2 * pair + 1) * (N_SP / 4) + s4];
        __half2* dst = y_sh + pair * STRIDE + s4 * 4;
        dst[0] = __floats2half2_rn(a.x, b.x);
        dst[1] = __floats2half2_rn(a.y, b.y);
        dst[2] = __floats2half2_rn(a.z, b.z);
        dst[3] = __floats2half2_rn(a.w, b.w);
    }

    // Wait for scatterK's grid to complete (memory visible after this).
    cudaGridDependencySynchronize();
    __syncthreads();

    // Read the warp's column lengths for both orders.
    int cnt1[COLS_PER_WARP], cnt2[COLS_PER_WARP];
#pragma unroll
    for (int cc = 0; cc < COLS_PER_WARP; ++cc) {
        int c1 = d_cursor[cbase + cc];
        int c2 = d_cursor[N_SP + cbase + cc];
        cnt1[cc] = c1 < CAP1 ? c1 : CAP1;
        cnt2[cc] = c2 < CAP2 ? c2 : CAP2;
    }

    const char* rowp = (const char*)(y_sh + lane * STRIDE);
    float resA[COLS_PER_WARP], resB[COLS_PER_WARP];

#pragma unroll
    for (int cc = 0; cc < COLS_PER_WARP; ++cc) {
        float aA0 = 0.f, aB0 = 0.f, aA1 = 0.f, aB1 = 0.f;

        // ---- 1st-order loop: uint4 = 2 records = 2 terms, one-ahead prefetch.
        // Rounded up to whole uint4 (zero pads contribute 0).
        {
            const uint4* p1 = (const uint4*)(d_rec1 + (size_t)(cbase + cc) * CAP1);
            int nb = (cnt1[cc] + 1) >> 1;
            uint4 q = p1[0];
            for (int k = 0; k < nb; ++k) {
                uint4 qn = p1[k + 1];      // one-past-end safe (+16 pad)
                term1(rowp, q.x, q.y, aA0, aB0);
                term1(rowp, q.z, q.w, aA1, aB1);
                q = qn;
            }
        }

        // ---- 2nd-order loop: quad = 2 uint4 = 2 depth-2 pair-chains, prefetch-1.
        // Rounded up to whole quads; zero-rate pads are exact no-ops -> no tail.
        {
            const uint4* rp = (const uint4*)(d_rec2 + (size_t)(cbase + cc) * CAP2);
            int nq = (cnt2[cc] + 3) >> 2;  // quads of 4 terms (2 uint4 each)
            uint4 a = rp[0], b = rp[1];
            for (int k = 0; k < nq; ++k) {
                uint4 an = rp[2 * k + 2];  // one-past-end safe (+16 pad)
                uint4 bn = rp[2 * k + 3];
                pair2(rowp, a, aA0, aB0);
                pair2(rowp, b, aA1, aB1);
                a = an; b = bn;
            }
        }
        resA[cc] = aA0 + aA1;
        resB[cc] = aB0 + aB1;
    }

    // Stores: 4 consecutive cols -> one float4 per row of the pair.
    float* opA = out + (size_t)(rg * ROWS_PER_CTA + 2 * lane) * N_SP + cbase;
    float* opB = opA + N_SP;
    *(float4*)opA = make_float4(resA[0], resA[1], resA[2], resA[3]);
    *(float4*)opB = make_float4(resB[0], resB[1], resB[2], resB[3]);

    // ---- End-of-run cursor re-zero (replaces the memset graph node). ----
    // All 128 CTAs are co-resident (1 CTA/SM, 128 <= 148): every CTA read its
    // counts right after the grid sync; we only zero after finishing the whole
    // ~25us gather, so no CTA can still be waiting to read them.
    __syncthreads();                       // this CTA's own count-reads are done
    if (blockIdx.x < 2) {
        d_cursor[blockIdx.x * 1024 + tid] = 0;
    }
}

// ---------------- launch ----------------

extern "C" void kernel_launch(void* const* d_in, const int* in_sizes, int n_in,
                              void* d_out, int out_size) {
    // metadata order: t_in, y_in, rates_1st, rates_2nd, den_norm,
    //                 inds_r1, inds_r2a, inds_r2b, inds_out1, inds_out2
    const float* y    = (const float*)d_in[1];
    const float* r1   = (const float*)d_in[2];
    const float* r2   = (const float*)d_in[3];
    const float* dn   = (const float*)d_in[4];
    const int*   ir1  = (const int*)d_in[5];
    const int*   ir2a = (const int*)d_in[6];
    const int*   ir2b = (const int*)d_in[7];
    const int*   io1  = (const int*)d_in[8];
    const int*   io2  = (const int*)d_in[9];
    float*       out  = (float*)d_out;

    int T1 = in_sizes[2];
    int T2 = in_sizes[3];
    int T  = T1 + T2;
    int B  = in_sizes[1] / N_SP;

    cudaFuncSetAttribute(mainK, cudaFuncAttributeMaxDynamicSharedMemorySize, SMEM_BYTES);

    // scatterK: normal launch (it triggers PDL completion at its start).
    scatterK<<<(T + 255) / 256, 256>>>(r1, r2, dn, ir1, ir2a, ir2b, io1, io2, T1, T2);

    // mainK: programmatic dependent launch -> its fill overlaps scatterK.
    cudaLaunchConfig_t cfg = {};
    cfg.gridDim  = dim3((B / ROWS_PER_CTA) * C_SPLIT, 1, 1);   // 128 CTAs
    cfg.blockDim = dim3(1024, 1, 1);
    cfg.dynamicSmemBytes = SMEM_BYTES;
    cfg.stream = 0;                        // legacy default stream (captured)
    cudaLaunchAttribute attrs[1];
    attrs[0].id = cudaLaunchAttributeProgrammaticStreamSerialization;
    attrs[0].val.programmaticStreamSerializationAllowed = 1;
    cfg.attrs = attrs;
    cfg.numAttrs = 1;
    cudaLaunchKernelEx(&cfg, mainK, y, out);
}